// round 2
// baseline (speedup 1.0000x reference)
#include <cuda_runtime.h>
#include <math.h>

#define CDIM 128
#define BT 64
#define NTHREADS 256
#define EPSF 1e-8f

// Device scratch (allocation-free rule): M = Wq @ Wk^T for both branches.
__device__ float g_M[2][CDIM * CDIM];

__device__ __forceinline__ float4 lds4(const float* p) {
    return *reinterpret_cast<const float4*>(p);
}

// ---------------------------------------------------------------------------
// Prep kernel: g_M[0] = Wq_m @ Wk_m^T, g_M[1] = Wq_d @ Wk_d^T
// grid: 256 blocks (which = bid>>7, row i = bid&127), 128 threads (p = tid)
// ---------------------------------------------------------------------------
__global__ void prep_kernel(const float* __restrict__ Wq_m, const float* __restrict__ Wk_m,
                            const float* __restrict__ Wq_d, const float* __restrict__ Wk_d) {
    __shared__ float qrow[CDIM];
    int which = blockIdx.x >> 7;
    int i = blockIdx.x & 127;
    const float* Wq = which ? Wq_d : Wq_m;
    const float* Wk = which ? Wk_d : Wk_m;
    if (threadIdx.x < CDIM) qrow[threadIdx.x] = Wq[i * CDIM + threadIdx.x];
    __syncthreads();
    int p = threadIdx.x;
    const float4* krow = reinterpret_cast<const float4*>(Wk + p * CDIM);
    float s = 0.f;
#pragma unroll
    for (int c4 = 0; c4 < CDIM / 4; ++c4) {
        float4 kv = krow[c4];
        s = fmaf(qrow[c4 * 4 + 0], kv.x, s);
        s = fmaf(qrow[c4 * 4 + 1], kv.y, s);
        s = fmaf(qrow[c4 * 4 + 2], kv.z, s);
        s = fmaf(qrow[c4 * 4 + 3], kv.w, s);
    }
    g_M[which][i * CDIM + p] = s;
}

// ---------------------------------------------------------------------------
// GEMM microkernel: acc[4][8] += A[64x128] @ W[128x128] tile.
// Thread (rg,cg): rows rbase..rbase+3, cols cbase..cbase+7.
// ---------------------------------------------------------------------------
__device__ __forceinline__ void gemm64(const float* __restrict__ As,
                                       const float* __restrict__ Ws,
                                       int rbase, int cbase, float acc[4][8]) {
#pragma unroll 1
    for (int k4 = 0; k4 < CDIM / 4; ++k4) {
        int k = k4 * 4;
        float a[4][4];
#pragma unroll
        for (int i = 0; i < 4; ++i) {
            float4 v = lds4(As + (rbase + i) * CDIM + k);
            a[i][0] = v.x; a[i][1] = v.y; a[i][2] = v.z; a[i][3] = v.w;
        }
#pragma unroll
        for (int kk = 0; kk < 4; ++kk) {
            float4 w0 = lds4(Ws + (k + kk) * CDIM + cbase);
            float4 w1 = lds4(Ws + (k + kk) * CDIM + cbase + 4);
            float wv[8] = {w0.x, w0.y, w0.z, w0.w, w1.x, w1.y, w1.z, w1.w};
#pragma unroll
            for (int i = 0; i < 4; ++i)
#pragma unroll
                for (int j = 0; j < 8; ++j)
                    acc[i][j] = fmaf(a[i][kk], wv[j], acc[i][j]);
        }
    }
}

// A is a per-row linear combination (ca[i]*M + cb[i]*D) built on the fly.
__device__ __forceinline__ void gemm64_comb(const float* __restrict__ Ma,
                                            const float* __restrict__ Db,
                                            const float* __restrict__ Ws,
                                            int rbase, int cbase,
                                            const float ca[4], const float cb[4],
                                            float acc[4][8]) {
#pragma unroll 1
    for (int k4 = 0; k4 < CDIM / 4; ++k4) {
        int k = k4 * 4;
        float a[4][4];
#pragma unroll
        for (int i = 0; i < 4; ++i) {
            float4 mv = lds4(Ma + (rbase + i) * CDIM + k);
            float4 dv = lds4(Db + (rbase + i) * CDIM + k);
            a[i][0] = ca[i] * mv.x + cb[i] * dv.x;
            a[i][1] = ca[i] * mv.y + cb[i] * dv.y;
            a[i][2] = ca[i] * mv.z + cb[i] * dv.z;
            a[i][3] = ca[i] * mv.w + cb[i] * dv.w;
        }
#pragma unroll
        for (int kk = 0; kk < 4; ++kk) {
            float4 w0 = lds4(Ws + (k + kk) * CDIM + cbase);
            float4 w1 = lds4(Ws + (k + kk) * CDIM + cbase + 4);
            float wv[8] = {w0.x, w0.y, w0.z, w0.w, w1.x, w1.y, w1.z, w1.w};
#pragma unroll
            for (int i = 0; i < 4; ++i)
#pragma unroll
                for (int j = 0; j < 8; ++j)
                    acc[i][j] = fmaf(a[i][kk], wv[j], acc[i][j]);
        }
    }
}

__device__ __forceinline__ void load_w(const float* __restrict__ g, float* s) {
    const float4* gs = reinterpret_cast<const float4*>(g);
    float4* ss = reinterpret_cast<float4*>(s);
    for (int i = threadIdx.x; i < CDIM * CDIM / 4; i += NTHREADS) ss[i] = gs[i];
}

// SMEM float offsets
#define OFF_M    0
#define OFF_D    8192
#define OFF_X1M  16384
#define OFF_X1D  24576
#define OFF_W    32768
#define OFF_R0   49152
#define OFF_R1   50176
#define OFF_SA   51200
#define OFF_SB   51264
#define OFF_W2   51328
#define SMEM_FLOATS 51456
#define SMEM_BYTES (SMEM_FLOATS * 4)

__global__ __launch_bounds__(NTHREADS, 1)
void mdi_kernel(const float* __restrict__ em, const float* __restrict__ ed,
                const float* __restrict__ Wgcn,
                const float* __restrict__ Wv_m, const float* __restrict__ Wv_d,
                const float* __restrict__ W1, const float* __restrict__ W2,
                float* __restrict__ out) {
    extern __shared__ float sh[];
    float* Ms  = sh + OFF_M;
    float* Ds  = sh + OFF_D;
    float* X1m = sh + OFF_X1M;
    float* X1d = sh + OFF_X1D;
    float* Ws  = sh + OFF_W;
    float* R0  = sh + OFF_R0;
    float* R1  = sh + OFF_R1;
    float* SA  = sh + OFF_SA;
    float* SB  = sh + OFF_SB;
    float* SW2 = sh + OFF_W2;

    const int tid = threadIdx.x;
    const int cg = tid & 15;
    const int rg = tid >> 4;
    const int rbase = rg * 4;
    const int cbase = cg * 8;
    const int b0 = blockIdx.x * BT;

    // ---- Load em/ed tiles + W2 ----
    {
        const float4* gm = reinterpret_cast<const float4*>(em + (size_t)b0 * CDIM);
        const float4* gd = reinterpret_cast<const float4*>(ed + (size_t)b0 * CDIM);
        float4* sm = reinterpret_cast<float4*>(Ms);
        float4* sd = reinterpret_cast<float4*>(Ds);
        for (int i = tid; i < BT * CDIM / 4; i += NTHREADS) { sm[i] = gm[i]; sd[i] = gd[i]; }
        if (tid < CDIM) SW2[tid] = W2[tid];
    }
    __syncthreads();

    // ---- E1: per-batch scalars (manhattan + cosine -> pL entries a, b) ----
    {
        int r = tid >> 2, part = tid & 3;
        const float* mrow = Ms + r * CDIM;
        const float* drow = Ds + r * CDIM;
        float dman = 0.f, sm2 = 0.f, sd2 = 0.f, md = 0.f;
        int k0 = part * 32;
#pragma unroll
        for (int k = 0; k < 32; k += 4) {
            float4 mv = lds4(mrow + k0 + k);
            float4 dv = lds4(drow + k0 + k);
            dman += fabsf(mv.x - dv.x) + fabsf(mv.y - dv.y) + fabsf(mv.z - dv.z) + fabsf(mv.w - dv.w);
            sm2 += mv.x * mv.x + mv.y * mv.y + mv.z * mv.z + mv.w * mv.w;
            sd2 += dv.x * dv.x + dv.y * dv.y + dv.z * dv.z + dv.w * dv.w;
            md  += mv.x * dv.x + mv.y * dv.y + mv.z * dv.z + mv.w * dv.w;
        }
        R0[0   + r * 4 + part] = dman;
        R0[256 + r * 4 + part] = sm2;
        R0[512 + r * 4 + part] = sd2;
        R0[768 + r * 4 + part] = md;
    }
    __syncthreads();
    if (tid < BT) {
        int b4 = tid * 4;
        float dman = R0[b4] + R0[b4 + 1] + R0[b4 + 2] + R0[b4 + 3];
        float sm2  = R0[256 + b4] + R0[257 + b4] + R0[258 + b4] + R0[259 + b4];
        float sd2  = R0[512 + b4] + R0[513 + b4] + R0[514 + b4] + R0[515 + b4];
        float md   = R0[768 + b4] + R0[769 + b4] + R0[770 + b4] + R0[771 + b4];
        // manhattan branch: dman >= 0 so lrelu is identity
        float s3 = 1.f / (1.f + dman);
        // cosine branch
        float c = md / (sqrtf(sm2 + EPSF) * sqrtf(sd2 + EPSF));
        if (c < 0.f) c *= 0.01f;            // leaky relu
        float s1 = 1.f / (1.f + c);          // deg = 1 + c >= 0.99 > EPS
        SA[tid] = fminf(s3, s1);             // diagonal of pL
        SB[tid] = fminf(dman * s3, c * s1);  // off-diagonal of pL
    }
    __syncthreads();

    // ---- S2: GCN. u0 = a*m + b*d ; u1 = b*m + a*d ; x1 = relu(u@Wgcn) + x0 ----
    load_w(Wgcn, Ws);
    __syncthreads();
    {
        float ca[4], cb[4];
#pragma unroll
        for (int i = 0; i < 4; ++i) { ca[i] = SA[rbase + i]; cb[i] = SB[rbase + i]; }

        float acc[4][8] = {{0.f}};
        gemm64_comb(Ms, Ds, Ws, rbase, cbase, ca, cb, acc);   // u0 @ Wgcn
#pragma unroll
        for (int i = 0; i < 4; ++i)
#pragma unroll
            for (int j = 0; j < 8; ++j) {
                int idx = (rbase + i) * CDIM + cbase + j;
                X1m[idx] = fmaxf(acc[i][j], 0.f) + Ms[idx];
            }

        float acc2[4][8] = {{0.f}};
        gemm64_comb(Ms, Ds, Ws, rbase, cbase, cb, ca, acc2);  // u1 @ Wgcn
#pragma unroll
        for (int i = 0; i < 4; ++i)
#pragma unroll
            for (int j = 0; j < 8; ++j) {
                int idx = (rbase + i) * CDIM + cbase + j;
                X1d[idx] = fmaxf(acc2[i][j], 0.f) + Ds[idx];
            }
    }
    __syncthreads();

    const float ISQRTC = 0.0883883476483184f;  // 1/sqrt(128)

    // ---- S4/S5 branch m: t = x1m@Mm; scores; softmax; z_m -> X1m ----
    load_w(g_M[0], Ws);
    __syncthreads();
    {
        float acc[4][8] = {{0.f}};
        gemm64(X1m, Ws, rbase, cbase, acc);
#pragma unroll
        for (int i = 0; i < 4; ++i) {
            float q0 = 0.f, q1 = 0.f;
#pragma unroll
            for (int j = 0; j < 8; ++j) {
                int idx = (rbase + i) * CDIM + cbase + j;
                q0 = fmaf(acc[i][j], Ms[idx], q0);
                q1 = fmaf(acc[i][j], X1m[idx], q1);
            }
            R0[(rbase + i) * 16 + cg] = q0;
            R1[(rbase + i) * 16 + cg] = q1;
        }
    }
    __syncthreads();
    if (tid < BT) {
        float s0 = 0.f, s1v = 0.f;
#pragma unroll
        for (int g = 0; g < 16; ++g) { s0 += R0[tid * 16 + g]; s1v += R1[tid * 16 + g]; }
        s0 *= ISQRTC; s1v *= ISQRTC;
        float mx = fmaxf(s0, s1v);
        float e0 = expf(s0 - mx), e1 = expf(s1v - mx);
        float inv = 1.f / (e0 + e1);
        SA[tid] = e0 * inv;
        SB[tid] = e1 * inv;
    }
    __syncthreads();
    {
        float4* xm = reinterpret_cast<float4*>(X1m);
        const float4* mm = reinterpret_cast<const float4*>(Ms);
        for (int i4 = tid; i4 < BT * CDIM / 4; i4 += NTHREADS) {
            int r = i4 >> 5;
            float a0 = SA[r], a1 = SB[r];
            float4 mv = mm[i4], xv = xm[i4];
            xv.x = a0 * mv.x + a1 * xv.x;
            xv.y = a0 * mv.y + a1 * xv.y;
            xv.z = a0 * mv.z + a1 * xv.z;
            xv.w = a0 * mv.w + a1 * xv.w;
            xm[i4] = xv;
        }
    }
    __syncthreads();

    // ---- S4/S5 branch d ----
    load_w(g_M[1], Ws);
    __syncthreads();
    {
        float acc[4][8] = {{0.f}};
        gemm64(X1d, Ws, rbase, cbase, acc);
#pragma unroll
        for (int i = 0; i < 4; ++i) {
            float q0 = 0.f, q1 = 0.f;
#pragma unroll
            for (int j = 0; j < 8; ++j) {
                int idx = (rbase + i) * CDIM + cbase + j;
                q0 = fmaf(acc[i][j], Ds[idx], q0);
                q1 = fmaf(acc[i][j], X1d[idx], q1);
            }
            R0[(rbase + i) * 16 + cg] = q0;
            R1[(rbase + i) * 16 + cg] = q1;
        }
    }
    __syncthreads();
    if (tid < BT) {
        float s0 = 0.f, s1v = 0.f;
#pragma unroll
        for (int g = 0; g < 16; ++g) { s0 += R0[tid * 16 + g]; s1v += R1[tid * 16 + g]; }
        s0 *= ISQRTC; s1v *= ISQRTC;
        float mx = fmaxf(s0, s1v);
        float e0 = expf(s0 - mx), e1 = expf(s1v - mx);
        float inv = 1.f / (e0 + e1);
        SA[tid] = e0 * inv;
        SB[tid] = e1 * inv;
    }
    __syncthreads();
    {
        float4* xd = reinterpret_cast<float4*>(X1d);
        const float4* dd = reinterpret_cast<const float4*>(Ds);
        for (int i4 = tid; i4 < BT * CDIM / 4; i4 += NTHREADS) {
            int r = i4 >> 5;
            float a0 = SA[r], a1 = SB[r];
            float4 dv = dd[i4], xv = xd[i4];
            xv.x = a0 * dv.x + a1 * xv.x;
            xv.y = a0 * dv.y + a1 * xv.y;
            xv.z = a0 * dv.z + a1 * xv.z;
            xv.w = a0 * dv.w + a1 * xv.w;
            xd[i4] = xv;
        }
    }
    __syncthreads();

    // ---- S6a: mLA = z_m @ Wv_m -> Ms (m no longer needed) ----
    load_w(Wv_m, Ws);
    __syncthreads();
    {
        float acc[4][8] = {{0.f}};
        gemm64(X1m, Ws, rbase, cbase, acc);
        __syncthreads();  // everyone done reading Ms before overwrite
#pragma unroll
        for (int i = 0; i < 4; ++i)
#pragma unroll
            for (int j = 0; j < 8; ++j)
                Ms[(rbase + i) * CDIM + cbase + j] = acc[i][j];
    }
    __syncthreads();

    // ---- S6b: ne = (z_d @ Wv_d) * mLA -> Ds ----
    load_w(Wv_d, Ws);
    __syncthreads();
    {
        float acc[4][8] = {{0.f}};
        gemm64(X1d, Ws, rbase, cbase, acc);
        __syncthreads();  // everyone done reading Ds before overwrite
#pragma unroll
        for (int i = 0; i < 4; ++i)
#pragma unroll
            for (int j = 0; j < 8; ++j) {
                int idx = (rbase + i) * CDIM + cbase + j;
                Ds[idx] = acc[i][j] * Ms[idx];
            }
    }
    __syncthreads();

    // ---- S7: pre = relu(ne @ W1) . W2 ; out = sigmoid(pre) ----
    load_w(W1, Ws);
    __syncthreads();
    {
        float acc[4][8] = {{0.f}};
        gemm64(Ds, Ws, rbase, cbase, acc);
#pragma unroll
        for (int i = 0; i < 4; ++i) {
            float q = 0.f;
#pragma unroll
            for (int j = 0; j < 8; ++j)
                q = fmaf(fmaxf(acc[i][j], 0.f), SW2[cbase + j], q);
            R0[(rbase + i) * 16 + cg] = q;
        }
    }
    __syncthreads();
    if (tid < BT) {
        float pre = 0.f;
#pragma unroll
        for (int g = 0; g < 16; ++g) pre += R0[tid * 16 + g];
        out[b0 + tid] = 1.f / (1.f + expf(-pre));
    }
}

extern "C" void kernel_launch(void* const* d_in, const int* in_sizes, int n_in,
                              void* d_out, int out_size) {
    const float* em    = (const float*)d_in[0];
    const float* ed    = (const float*)d_in[1];
    const float* Wgcn  = (const float*)d_in[2];
    const float* Wq_m  = (const float*)d_in[3];
    const float* Wk_m  = (const float*)d_in[4];
    const float* Wv_m  = (const float*)d_in[5];
    const float* Wq_d  = (const float*)d_in[6];
    const float* Wk_d  = (const float*)d_in[7];
    const float* Wv_d  = (const float*)d_in[8];
    const float* W1    = (const float*)d_in[9];
    const float* W2    = (const float*)d_in[10];
    float* out = (float*)d_out;

    cudaFuncSetAttribute(mdi_kernel, cudaFuncAttributeMaxDynamicSharedMemorySize, SMEM_BYTES);

    int B = out_size;                // 262144
    prep_kernel<<<256, 128>>>(Wq_m, Wk_m, Wq_d, Wk_d);
    mdi_kernel<<<B / BT, NTHREADS, SMEM_BYTES>>>(em, ed, Wgcn, Wv_m, Wv_d, W1, W2, out);
}